// round 4
// baseline (speedup 1.0000x reference)
#include <cuda_runtime.h>
#include <cuda_bf16.h>

#define NMAX   50000
#define FEATN  128
#define POOLW  384   // 3*128
#define NGRAPH 128

// ---------------- scratch (static device globals; no allocation) -------------
__device__ __align__(256) float g_deg [NMAX];
__device__ __align__(256) float g_dis [NMAX];
__device__ __align__(256) float g_hs  [NMAX * FEATN];   // dis[r] * (x @ W)
__device__ __align__(256) float g_agg [NMAX * FEATN];   // aggregation (init = self loop)
__device__ __align__(256) float g_x1  [NMAX * FEATN];
__device__ __align__(256) float g_x2  [NMAX * FEATN];
__device__ __align__(256) float g_pool[NGRAPH * POOLW]; // pooled rep (atomics live here)

__global__ void zero_pool_kernel() {
    int i = blockIdx.x * blockDim.x + threadIdx.x;
    if (i < NGRAPH * POOLW) g_pool[i] = 0.0f;
}

__global__ void init_deg_kernel(int n) {
    int i = blockIdx.x * blockDim.x + threadIdx.x;
    if (i < n) g_deg[i] = 1.0f;   // self loop
}

__global__ void edge_deg_kernel(const int* __restrict__ ei_col, int E) {
    int e = blockIdx.x * blockDim.x + threadIdx.x;
    if (e < E) atomicAdd(&g_deg[ei_col[e]], 1.0f);
}

__global__ void dis_kernel(int n) {
    int i = blockIdx.x * blockDim.x + threadIdx.x;
    if (i < n) g_dis[i] = rsqrtf(g_deg[i]);
}

// ---------------- GEMM: h = X @ W, epilogue writes hs=dis*h, agg=dis*hs ------
// tile: 64 rows x 128 cols, 256 threads. warp w owns rows [w*8, w*8+8), all cols.
#define TM 64
#define TK 32
__global__ __launch_bounds__(256) void gemm_layer_kernel(
    int xsel, const float* __restrict__ Xin, const float* __restrict__ W, int N)
{
    const float* X = (xsel == 0) ? Xin : (xsel == 1 ? g_x1 : g_x2);

    __shared__ float sX[TM][TK + 4];
    __shared__ float sW[TK][FEATN];

    int tid  = threadIdx.x;
    int row0 = blockIdx.x * TM;
    int cg   = tid & 31;     // column group (4 cols each)
    int rg   = tid >> 5;     // row group (8 rows each) == warp id

    float acc[8][4];
    #pragma unroll
    for (int i = 0; i < 8; i++)
        { acc[i][0]=0.f; acc[i][1]=0.f; acc[i][2]=0.f; acc[i][3]=0.f; }

    for (int kc = 0; kc < FEATN; kc += TK) {
        #pragma unroll
        for (int i = 0; i < 2; i++) {
            int idx = tid + i * 256;
            int r   = idx >> 3;
            int c4  = (idx & 7) * 4;
            float4 v = make_float4(0.f, 0.f, 0.f, 0.f);
            int gr = row0 + r;
            if (gr < N) v = *(const float4*)(X + (long)gr * FEATN + kc + c4);
            sX[r][c4]   = v.x; sX[r][c4+1] = v.y;
            sX[r][c4+2] = v.z; sX[r][c4+3] = v.w;
        }
        #pragma unroll
        for (int i = 0; i < 4; i++) {
            int idx = tid + i * 256;
            int r   = idx >> 5;
            int c4  = (idx & 31) * 4;
            *(float4*)(&sW[r][c4]) = *(const float4*)(W + (long)(kc + r) * FEATN + c4);
        }
        __syncthreads();

        #pragma unroll
        for (int k = 0; k < TK; k++) {
            float a[8];
            #pragma unroll
            for (int i = 0; i < 8; i++) a[i] = sX[rg * 8 + i][k];
            float4 b = *(float4*)(&sW[k][cg * 4]);
            #pragma unroll
            for (int i = 0; i < 8; i++) {
                acc[i][0] += a[i] * b.x;
                acc[i][1] += a[i] * b.y;
                acc[i][2] += a[i] * b.z;
                acc[i][3] += a[i] * b.w;
            }
        }
        __syncthreads();
    }

    #pragma unroll
    for (int i = 0; i < 8; i++) {
        int gr = row0 + rg * 8 + i;
        if (gr < N) {
            float d = g_dis[gr];
            float4 h;
            h.x = acc[i][0] * d; h.y = acc[i][1] * d;
            h.z = acc[i][2] * d; h.w = acc[i][3] * d;
            *(float4*)(g_hs + (long)gr * FEATN + cg * 4) = h;
            float4 o;
            o.x = h.x * d; o.y = h.y * d; o.z = h.z * d; o.w = h.w * d;
            *(float4*)(g_agg + (long)gr * FEATN + cg * 4) = o;
        }
    }
}

// ---------------- edge scatter: agg[col] += dis[col] * hs[row] ---------------
// one warp per edge; lane handles 4 feats
__global__ __launch_bounds__(256) void scatter_kernel(
    const int* __restrict__ ei, int E)
{
    long idx = (long)blockIdx.x * blockDim.x + threadIdx.x;
    int e = (int)(idx >> 5);
    if (e >= E) return;
    int lane = (int)(idx & 31);

    int r = ei[e];
    int c = ei[E + e];
    float nc = g_dis[c];

    float4 v = *(const float4*)(g_hs + (long)r * FEATN + lane * 4);
    float* p = g_agg + (long)c * FEATN + lane * 4;
    atomicAdd(p + 0, v.x * nc);
    atomicAdd(p + 1, v.y * nc);
    atomicAdd(p + 2, v.z * nc);
    atomicAdd(p + 3, v.w * nc);
}

// ---------------- finalize: x_next = relu(agg + b); g_pool += x_next ---------
// one warp per node. outsel: 1 -> g_x1, 2 -> g_x2, 3 -> x3out (plain stores)
__global__ __launch_bounds__(256) void finalize_kernel(
    const float* __restrict__ b, int outsel, float* __restrict__ x3out,
    const int* __restrict__ batch, int N, int pool_off)
{
    long idx = (long)blockIdx.x * blockDim.x + threadIdx.x;
    int i = (int)(idx >> 5);
    if (i >= N) return;
    int lane = (int)(idx & 31);

    float* xnext = (outsel == 1) ? g_x1 : (outsel == 2 ? g_x2 : x3out);

    float4 bv = *(const float4*)(b + lane * 4);
    float4 v  = *(const float4*)(g_agg + (long)i * FEATN + lane * 4);
    v.x = fmaxf(v.x + bv.x, 0.f);
    v.y = fmaxf(v.y + bv.y, 0.f);
    v.z = fmaxf(v.z + bv.z, 0.f);
    v.w = fmaxf(v.w + bv.w, 0.f);
    *(float4*)(xnext + (long)i * FEATN + lane * 4) = v;

    int g = batch[i];
    float* p = g_pool + (long)g * POOLW + pool_off + lane * 4;
    atomicAdd(p + 0, v.x);
    atomicAdd(p + 1, v.y);
    atomicAdd(p + 2, v.z);
    atomicAdd(p + 3, v.w);
}

__global__ void copy_pool_kernel(float* __restrict__ out) {
    int i = blockIdx.x * blockDim.x + threadIdx.x;
    if (i < NGRAPH * POOLW) out[i] = g_pool[i];
}

// ---------------- launch ------------------------------------------------------
extern "C" void kernel_launch(void* const* d_in, const int* in_sizes, int n_in,
                              void* d_out, int out_size)
{
    const float* x     = (const float*)d_in[0];
    const int*   ei    = (const int*)d_in[1];    // int32! (JAX x64 disabled)
    const int*   batch = (const int*)d_in[2];
    const float* W0    = (const float*)d_in[3];
    const float* b0    = (const float*)d_in[4];
    const float* W1    = (const float*)d_in[5];
    const float* b1    = (const float*)d_in[6];
    const float* W2    = (const float*)d_in[7];
    const float* b2    = (const float*)d_in[8];

    int N = in_sizes[0] / FEATN;     // 50000
    int E = in_sizes[1] / 2;         // 800000
    int pool_elems = NGRAPH * POOLW; // 49152

    float* out  = (float*)d_out;
    float* x3   = out + pool_elems;

    // prep
    zero_pool_kernel<<<(pool_elems + 255) / 256, 256>>>();
    init_deg_kernel<<<(N + 255) / 256, 256>>>(N);
    edge_deg_kernel<<<(E + 255) / 256, 256>>>(ei + E, E);   // col = second row
    dis_kernel<<<(N + 255) / 256, 256>>>(N);

    int gemm_blocks    = (N + TM - 1) / TM;
    long scat_threads  = (long)E * 32;
    int scat_blocks    = (int)((scat_threads + 255) / 256);
    long fin_threads   = (long)N * 32;
    int fin_blocks     = (int)((fin_threads + 255) / 256);

    // layer 1
    gemm_layer_kernel<<<gemm_blocks, 256>>>(0, x, W0, N);
    scatter_kernel<<<scat_blocks, 256>>>(ei, E);
    finalize_kernel<<<fin_blocks, 256>>>(b0, 1, nullptr, batch, N, 0);

    // layer 2
    gemm_layer_kernel<<<gemm_blocks, 256>>>(1, nullptr, W1, N);
    scatter_kernel<<<scat_blocks, 256>>>(ei, E);
    finalize_kernel<<<fin_blocks, 256>>>(b1, 2, nullptr, batch, N, 128);

    // layer 3
    gemm_layer_kernel<<<gemm_blocks, 256>>>(2, nullptr, W2, N);
    scatter_kernel<<<scat_blocks, 256>>>(ei, E);
    finalize_kernel<<<fin_blocks, 256>>>(b2, 3, x3, batch, N, 256);

    // pool -> d_out (plain stores only)
    copy_pool_kernel<<<(pool_elems + 255) / 256, 256>>>(out);
}

// round 6
// speedup vs baseline: 2.1358x; 2.1358x over previous
#include <cuda_runtime.h>
#include <cuda_bf16.h>

#define NMAX   50000
#define EMAX   800000
#define FEATN  128
#define POOLW  384   // 3*128
#define NGRAPH 128
#define SCAN_T 1024

// ---------------- scratch (static device globals; no allocation) -------------
__device__ __align__(256) float g_dis [NMAX];
__device__ __align__(256) int   g_cnt [NMAX];
__device__ __align__(256) int   g_fill[NMAX];
__device__ __align__(256) int   g_off [NMAX + 1];
__device__ __align__(256) int   g_src [EMAX];
__device__ __align__(256) float g_hs  [NMAX * FEATN];   // dis[r] * (x @ W)
__device__ __align__(256) float g_x1  [NMAX * FEATN];
__device__ __align__(256) float g_x2  [NMAX * FEATN];
__device__ __align__(256) float g_pool[NGRAPH * POOLW];

// ---------------- prep: counts, scan, fill, dis ------------------------------
__global__ void zero_kernel(int n) {
    int i = blockIdx.x * blockDim.x + threadIdx.x;
    if (i < NGRAPH * POOLW) g_pool[i] = 0.0f;
    if (i < n) { g_cnt[i] = 0; g_fill[i] = 0; }
}

__global__ void count_kernel(const int* __restrict__ ei_col, int E) {
    int e = blockIdx.x * blockDim.x + threadIdx.x;
    if (e < E) atomicAdd(&g_cnt[ei_col[e]], 1);
}

// single-block exclusive scan of g_cnt -> g_off; also dis = rsqrt(1+cnt)
__global__ __launch_bounds__(SCAN_T) void scan_kernel(int n) {
    __shared__ int ssum[SCAN_T];
    int tid = threadIdx.x;
    int chunk = (n + SCAN_T - 1) / SCAN_T;
    int lo = tid * chunk;
    int hi = min(lo + chunk, n);
    int s = 0;
    for (int i = lo; i < hi; i++) s += g_cnt[i];
    ssum[tid] = s;
    __syncthreads();
    for (int d = 1; d < SCAN_T; d <<= 1) {
        int v = (tid >= d) ? ssum[tid - d] : 0;
        __syncthreads();
        ssum[tid] += v;
        __syncthreads();
    }
    int base = (tid > 0) ? ssum[tid - 1] : 0;
    for (int i = lo; i < hi; i++) {
        g_off[i] = base;
        g_dis[i] = rsqrtf(1.0f + (float)g_cnt[i]);
        base += g_cnt[i];
    }
    if (tid == SCAN_T - 1) g_off[n] = base;
}

__global__ void fill_kernel(const int* __restrict__ ei, int E) {
    int e = blockIdx.x * blockDim.x + threadIdx.x;
    if (e < E) {
        int c = ei[E + e];
        int pos = g_off[c] + atomicAdd(&g_fill[c], 1);
        g_src[pos] = ei[e];
    }
}

// ---------------- GEMM: hs = dis * (X @ W) -----------------------------------
// tile: 64 rows x 128 cols, 256 threads; thread = 8 rows x 4 cols.
#define TM 64
#define TK 32
__global__ __launch_bounds__(256) void gemm_layer_kernel(
    int xsel, const float* __restrict__ Xin, const float* __restrict__ W, int N)
{
    const float* X = (xsel == 0) ? Xin : (xsel == 1 ? g_x1 : g_x2);

    __shared__ float sX[TM][TK + 4];
    __shared__ float sW[TK][FEATN];

    int tid  = threadIdx.x;
    int row0 = blockIdx.x * TM;
    int cg   = tid & 31;
    int rg   = tid >> 5;

    float acc[8][4];
    #pragma unroll
    for (int i = 0; i < 8; i++)
        { acc[i][0]=0.f; acc[i][1]=0.f; acc[i][2]=0.f; acc[i][3]=0.f; }

    for (int kc = 0; kc < FEATN; kc += TK) {
        #pragma unroll
        for (int i = 0; i < 2; i++) {
            int idx = tid + i * 256;
            int r   = idx >> 3;
            int c4  = (idx & 7) * 4;
            float4 v = make_float4(0.f, 0.f, 0.f, 0.f);
            int gr = row0 + r;
            if (gr < N) v = *(const float4*)(X + (long)gr * FEATN + kc + c4);
            sX[r][c4]   = v.x; sX[r][c4+1] = v.y;
            sX[r][c4+2] = v.z; sX[r][c4+3] = v.w;
        }
        #pragma unroll
        for (int i = 0; i < 4; i++) {
            int idx = tid + i * 256;
            int r   = idx >> 5;
            int c4  = (idx & 31) * 4;
            *(float4*)(&sW[r][c4]) = *(const float4*)(W + (long)(kc + r) * FEATN + c4);
        }
        __syncthreads();

        #pragma unroll
        for (int k = 0; k < TK; k++) {
            float a[8];
            #pragma unroll
            for (int i = 0; i < 8; i++) a[i] = sX[rg * 8 + i][k];
            float4 b = *(float4*)(&sW[k][cg * 4]);
            #pragma unroll
            for (int i = 0; i < 8; i++) {
                acc[i][0] += a[i] * b.x;
                acc[i][1] += a[i] * b.y;
                acc[i][2] += a[i] * b.z;
                acc[i][3] += a[i] * b.w;
            }
        }
        __syncthreads();
    }

    #pragma unroll
    for (int i = 0; i < 8; i++) {
        int gr = row0 + rg * 8 + i;
        if (gr < N) {
            float d = g_dis[gr];
            float4 h;
            h.x = acc[i][0] * d; h.y = acc[i][1] * d;
            h.z = acc[i][2] * d; h.w = acc[i][3] * d;
            *(float4*)(g_hs + (long)gr * FEATN + cg * 4) = h;
        }
    }
}

// ---------------- gather + finalize (fused) ----------------------------------
// warp per node: out = relu(dis[i]*(sum_in hs[r] + hs[i]) + b); pool += out
__global__ __launch_bounds__(256) void gather_kernel(
    const float* __restrict__ b, int outsel, float* __restrict__ x3out,
    const int* __restrict__ batch, int N, int pool_off)
{
    long idx = (long)blockIdx.x * blockDim.x + threadIdx.x;
    int i = (int)(idx >> 5);
    if (i >= N) return;
    int lane = (int)(idx & 31);
    int l4 = lane * 4;

    float* xnext = (outsel == 1) ? g_x1 : (outsel == 2 ? g_x2 : x3out);

    // self loop term (hs already carries dis[i])
    float4 acc = *(const float4*)(g_hs + (long)i * FEATN + l4);

    int s0 = g_off[i];
    int s1 = g_off[i + 1];
    int k = s0;
    // 4-way unroll for memory-level parallelism
    for (; k + 4 <= s1; k += 4) {
        int r0 = g_src[k], r1 = g_src[k+1], r2 = g_src[k+2], r3 = g_src[k+3];
        float4 v0 = *(const float4*)(g_hs + (long)r0 * FEATN + l4);
        float4 v1 = *(const float4*)(g_hs + (long)r1 * FEATN + l4);
        float4 v2 = *(const float4*)(g_hs + (long)r2 * FEATN + l4);
        float4 v3 = *(const float4*)(g_hs + (long)r3 * FEATN + l4);
        acc.x += v0.x + v1.x + v2.x + v3.x;
        acc.y += v0.y + v1.y + v2.y + v3.y;
        acc.z += v0.z + v1.z + v2.z + v3.z;
        acc.w += v0.w + v1.w + v2.w + v3.w;
    }
    for (; k < s1; k++) {
        int r = g_src[k];
        float4 v = *(const float4*)(g_hs + (long)r * FEATN + l4);
        acc.x += v.x; acc.y += v.y; acc.z += v.z; acc.w += v.w;
    }

    float d = g_dis[i];
    float4 bv = *(const float4*)(b + l4);
    float4 o;
    o.x = fmaxf(acc.x * d + bv.x, 0.f);
    o.y = fmaxf(acc.y * d + bv.y, 0.f);
    o.z = fmaxf(acc.z * d + bv.z, 0.f);
    o.w = fmaxf(acc.w * d + bv.w, 0.f);
    *(float4*)(xnext + (long)i * FEATN + l4) = o;

    int g = batch[i];
    float* p = g_pool + (long)g * POOLW + pool_off + l4;
    atomicAdd(p + 0, o.x);
    atomicAdd(p + 1, o.y);
    atomicAdd(p + 2, o.z);
    atomicAdd(p + 3, o.w);
}

__global__ void copy_pool_kernel(float* __restrict__ out) {
    int i = blockIdx.x * blockDim.x + threadIdx.x;
    if (i < NGRAPH * POOLW) out[i] = g_pool[i];
}

// ---------------- launch ------------------------------------------------------
extern "C" void kernel_launch(void* const* d_in, const int* in_sizes, int n_in,
                              void* d_out, int out_size)
{
    const float* x     = (const float*)d_in[0];
    const int*   ei    = (const int*)d_in[1];    // int32 (JAX x64 disabled)
    const int*   batch = (const int*)d_in[2];
    const float* W0    = (const float*)d_in[3];
    const float* b0    = (const float*)d_in[4];
    const float* W1    = (const float*)d_in[5];
    const float* b1    = (const float*)d_in[6];
    const float* W2    = (const float*)d_in[7];
    const float* b2    = (const float*)d_in[8];

    int N = in_sizes[0] / FEATN;     // 50000
    int E = in_sizes[1] / 2;         // 800000
    int pool_elems = NGRAPH * POOLW; // 49152

    float* out = (float*)d_out;
    float* x3  = out + pool_elems;

    // prep: zero, count, scan(+dis), fill  (CSR built once, reused 3x)
    zero_kernel<<<(N + 255) / 256, 256>>>(N);
    count_kernel<<<(E + 255) / 256, 256>>>(ei + E, E);
    scan_kernel<<<1, SCAN_T>>>(N);
    fill_kernel<<<(E + 255) / 256, 256>>>(ei, E);

    int gemm_blocks  = (N + TM - 1) / TM;
    long gat_threads = (long)N * 32;
    int gat_blocks   = (int)((gat_threads + 255) / 256);

    // layer 1
    gemm_layer_kernel<<<gemm_blocks, 256>>>(0, x, W0, N);
    gather_kernel<<<gat_blocks, 256>>>(b0, 1, nullptr, batch, N, 0);

    // layer 2
    gemm_layer_kernel<<<gemm_blocks, 256>>>(1, nullptr, W1, N);
    gather_kernel<<<gat_blocks, 256>>>(b1, 2, nullptr, batch, N, 128);

    // layer 3
    gemm_layer_kernel<<<gemm_blocks, 256>>>(2, nullptr, W2, N);
    gather_kernel<<<gat_blocks, 256>>>(b2, 3, x3, batch, N, 256);

    // pool -> d_out (plain stores only)
    copy_pool_kernel<<<(pool_elems + 255) / 256, 256>>>(out);
}